// round 1
// baseline (speedup 1.0000x reference)
#include <cuda_runtime.h>
#include <cuda_bf16.h>
#include <cstdint>

#define C 80
#define KB 64                 // items per CTA k-tile
#define PITCH_HALF 68         // halves per class row (KB + 4 pad) -> 136 bytes
#define PITCH_PAIR (PITCH_HALF/2)
#define NWARPS 10             // 5 M-tiles x 2 K-groups
#define NTHREADS 320
#define GRID 304              // ~2 CTAs per SM (152 SMs), grid-stride over tiles

__device__ float g_cooc[C * C];

__global__ void zero_kernel() {
    int i = blockIdx.x * blockDim.x + threadIdx.x;
    if (i < C * C) g_cooc[i] = 0.0f;
}

__global__ __launch_bounds__(NTHREADS, 2)
void cooc_kernel(const float* __restrict__ label, int batch) {
    __shared__ __nv_bfloat16 sT[C * PITCH_HALF];   // [class][item] bf16, transposed tile

    const int tid  = threadIdx.x;
    const int warp = tid >> 5;
    const int lane = tid & 31;
    const int mt   = warp % 5;   // M tile (rows mt*16 .. mt*16+15)
    const int kg   = warp / 5;   // k-group within tile (0: items 0..31, 1: 32..63)
    const int g    = lane >> 2;  // groupID
    const int t    = lane & 3;   // threadID in group

    // accumulators: 10 N-tiles of m16n8, 4 f32 each
    float d[10][4];
    #pragma unroll
    for (int n = 0; n < 10; n++)
        #pragma unroll
        for (int q = 0; q < 4; q++) d[n][q] = 0.0f;

    const uint32_t* sB = (const uint32_t*)sT;      // bf16x2 pair view, pitch PITCH_PAIR

    const int numTiles = (batch + KB - 1) / KB;
    for (int tile = blockIdx.x; tile < numTiles; tile += gridDim.x) {
        const long long base = (long long)tile * KB * C;

        // ---- load KB x 80 f32 coalesced, convert to bf16, store transposed ----
        // KB*C/4 = 1280 float4 loads across 320 threads -> 4 each
        #pragma unroll
        for (int p = 0; p < (KB * C / 4) / NTHREADS; p++) {
            int idx  = tid + p * NTHREADS;
            int item = idx / (C / 4);
            int c4   = (idx % (C / 4)) * 4;
            float4 v;
            if (tile * KB + item < batch) {
                v = *(const float4*)(label + base + (long long)item * C + c4);
            } else {
                v = make_float4(0.f, 0.f, 0.f, 0.f);
            }
            sT[(c4 + 0) * PITCH_HALF + item] = __float2bfloat16(v.x);
            sT[(c4 + 1) * PITCH_HALF + item] = __float2bfloat16(v.y);
            sT[(c4 + 2) * PITCH_HALF + item] = __float2bfloat16(v.z);
            sT[(c4 + 3) * PITCH_HALF + item] = __float2bfloat16(v.w);
        }
        __syncthreads();

        // ---- MMA: D[16x80] += A[16xk] * B[kx80] for this warp's k-group ----
        #pragma unroll
        for (int ks = 0; ks < 2; ks++) {
            const int k0  = kg * 32 + ks * 16;
            const int kc0 = (k0 >> 1) + t;          // pair index of col (k0 + 2t)

            const int rowA  = mt * 16 + g;
            uint32_t a0 = sB[(rowA)     * PITCH_PAIR + kc0];
            uint32_t a1 = sB[(rowA + 8) * PITCH_PAIR + kc0];
            uint32_t a2 = sB[(rowA)     * PITCH_PAIR + kc0 + 4];  // k+8
            uint32_t a3 = sB[(rowA + 8) * PITCH_PAIR + kc0 + 4];

            #pragma unroll
            for (int nt = 0; nt < 10; nt++) {
                const int rowB = nt * 8 + g;
                uint32_t b0 = sB[rowB * PITCH_PAIR + kc0];
                uint32_t b1 = sB[rowB * PITCH_PAIR + kc0 + 4];
                asm volatile(
                    "mma.sync.aligned.m16n8k16.row.col.f32.bf16.bf16.f32 "
                    "{%0,%1,%2,%3}, {%4,%5,%6,%7}, {%8,%9}, {%0,%1,%2,%3};\n"
                    : "+f"(d[nt][0]), "+f"(d[nt][1]), "+f"(d[nt][2]), "+f"(d[nt][3])
                    : "r"(a0), "r"(a1), "r"(a2), "r"(a3), "r"(b0), "r"(b1));
            }
        }
        __syncthreads();
    }

    // ---- flush partials (integer-valued f32 -> exact, order-independent) ----
    #pragma unroll
    for (int nt = 0; nt < 10; nt++) {
        const int row = mt * 16 + g;
        const int col = nt * 8 + 2 * t;
        atomicAdd(&g_cooc[(row)     * C + col],     d[nt][0]);
        atomicAdd(&g_cooc[(row)     * C + col + 1], d[nt][1]);
        atomicAdd(&g_cooc[(row + 8) * C + col],     d[nt][2]);
        atomicAdd(&g_cooc[(row + 8) * C + col + 1], d[nt][3]);
    }
}

__global__ void finalize_kernel(const float* __restrict__ pre_adj, float* __restrict__ out) {
    __shared__ float red[256];
    const int tid = threadIdx.x;
    float sum = 0.0f;
    for (int idx = tid; idx < C * C; idx += 256) {
        int i = idx / C, j = idx % C;
        float cooc = g_cooc[idx];
        float cnt  = g_cooc[i * C + i];          // diagonal = per-class count
        float adj  = (i == j) ? 1.0f : cooc / (cnt + 1e-7f);
        float r = fabsf(pre_adj[idx] - adj);
        sum += (r < 1.0f) ? (r * r) : (r - 0.5f);
    }
    red[tid] = sum;
    __syncthreads();
    for (int s = 128; s > 0; s >>= 1) {
        if (tid < s) red[tid] += red[tid + s];
        __syncthreads();
    }
    if (tid == 0) out[0] = red[0] / (float)(C * C);
}

extern "C" void kernel_launch(void* const* d_in, const int* in_sizes, int n_in,
                              void* d_out, int out_size) {
    const float* pre_adj = (const float*)d_in[0];
    const float* label   = (const float*)d_in[1];
    const int batch = in_sizes[1] / C;

    zero_kernel<<<(C * C + 255) / 256, 256>>>();
    cooc_kernel<<<GRID, NTHREADS>>>(label, batch);
    finalize_kernel<<<1, 256>>>(pre_adj, (float*)d_out);
}

// round 2
// speedup vs baseline: 1.5314x; 1.5314x over previous
#include <cuda_runtime.h>
#include <cuda_bf16.h>
#include <cstdint>

#define C 80
#define KB 128                 // items per CTA tile
#define PITCH 88               // halves per item row (80 + 8 pad) -> 176 B, conflict-free for ldmatrix
#define NWARPS 10              // 5 M-tiles x 2 K-groups (64 items each)
#define NTHREADS 320
#define GRID 304               // 2 CTAs per SM, grid-stride over tiles

__device__ float g_cooc[C * C];

__global__ __launch_bounds__(NTHREADS, 2)
void cooc_kernel(const float* __restrict__ label, int batch) {
    __shared__ __nv_bfloat16 sT[KB * PITCH];   // natural [item][class] bf16

    const int tid  = threadIdx.x;
    const int warp = tid >> 5;
    const int lane = tid & 31;
    const int mt   = warp % 5;   // M tile: classes mt*16 .. mt*16+15
    const int kg   = warp / 5;   // item group: kg*64 .. kg*64+63
    const int g    = lane >> 2;
    const int t    = lane & 3;
    const int gi   = lane >> 3;  // ldmatrix group 0..3
    const int li   = lane & 7;   // lane within group

    // smem u32 address base for ldmatrix
    uint32_t smem_u32;
    { uint64_t tmp; asm("cvta.to.shared.u64 %0, %1;" : "=l"(tmp) : "l"((void*)sT));
      smem_u32 = (uint32_t)tmp; }

    // Per-lane invariant address pieces (halves -> bytes at the end)
    // A groups: class off = mt*16 + ((gi&1)?8:0); item off = ((gi&2)?8:0) + li
    const int a_cls   = mt * 16 + ((gi & 1) ? 8 : 0);
    const int a_kbase = ((gi & 2) ? 8 : 0) + li;
    // B groups: class off = n0 + ((gi&2)?8:0); item off = ((gi&1)?8:0) + li
    const int b_clsadd = (gi & 2) ? 8 : 0;
    const int b_kbase  = ((gi & 1) ? 8 : 0) + li;

    float d[10][4];
    #pragma unroll
    for (int n = 0; n < 10; n++)
        #pragma unroll
        for (int q = 0; q < 4; q++) d[n][q] = 0.0f;

    const int numTiles = (batch + KB - 1) / KB;
    for (int tile = blockIdx.x; tile < numTiles; tile += gridDim.x) {
        const long long base = (long long)tile * KB * C;

        // ---- load KB x 80 f32 coalesced, convert pairwise, store natural layout ----
        // KB*C/4 = 2560 float4 across 320 threads -> 8 each
        #pragma unroll
        for (int p = 0; p < (KB * C / 4) / NTHREADS; p++) {
            int idx  = tid + p * NTHREADS;
            int item = idx / (C / 4);
            int c4   = (idx % (C / 4)) * 4;
            float4 v;
            if (tile * KB + item < batch) {
                v = *(const float4*)(label + base + (long long)item * C + c4);
            } else {
                v = make_float4(0.f, 0.f, 0.f, 0.f);
            }
            uint32_t lo, hi;
            asm("cvt.rn.bf16x2.f32 %0, %1, %2;" : "=r"(lo) : "f"(v.y), "f"(v.x));
            asm("cvt.rn.bf16x2.f32 %0, %1, %2;" : "=r"(hi) : "f"(v.w), "f"(v.z));
            *(uint2*)&sT[item * PITCH + c4] = make_uint2(lo, hi);
        }
        __syncthreads();

        // ---- MMA: ldmatrix.trans pulls [class][item] fragments from natural layout ----
        #pragma unroll
        for (int ks = 0; ks < 4; ks++) {
            const int k0 = kg * 64 + ks * 16;

            uint32_t a0, a1, a2, a3;
            {
                uint32_t addr = smem_u32 + (uint32_t)(((k0 + a_kbase) * PITCH + a_cls) * 2);
                asm volatile("ldmatrix.sync.aligned.m8n8.x4.trans.shared.b16 "
                             "{%0,%1,%2,%3}, [%4];"
                             : "=r"(a0), "=r"(a1), "=r"(a2), "=r"(a3) : "r"(addr));
            }

            #pragma unroll
            for (int p = 0; p < 5; p++) {
                const int n0 = p * 16;
                uint32_t b0, b1, b2, b3;
                uint32_t addr = smem_u32 + (uint32_t)(((k0 + b_kbase) * PITCH + n0 + b_clsadd) * 2);
                asm volatile("ldmatrix.sync.aligned.m8n8.x4.trans.shared.b16 "
                             "{%0,%1,%2,%3}, [%4];"
                             : "=r"(b0), "=r"(b1), "=r"(b2), "=r"(b3) : "r"(addr));
                asm volatile(
                    "mma.sync.aligned.m16n8k16.row.col.f32.bf16.bf16.f32 "
                    "{%0,%1,%2,%3}, {%4,%5,%6,%7}, {%8,%9}, {%0,%1,%2,%3};\n"
                    : "+f"(d[2*p][0]), "+f"(d[2*p][1]), "+f"(d[2*p][2]), "+f"(d[2*p][3])
                    : "r"(a0), "r"(a1), "r"(a2), "r"(a3), "r"(b0), "r"(b1));
                asm volatile(
                    "mma.sync.aligned.m16n8k16.row.col.f32.bf16.bf16.f32 "
                    "{%0,%1,%2,%3}, {%4,%5,%6,%7}, {%8,%9}, {%0,%1,%2,%3};\n"
                    : "+f"(d[2*p+1][0]), "+f"(d[2*p+1][1]), "+f"(d[2*p+1][2]), "+f"(d[2*p+1][3])
                    : "r"(a0), "r"(a1), "r"(a2), "r"(a3), "r"(b2), "r"(b3));
            }
        }
        __syncthreads();
    }

    // ---- flush partials (integer-valued f32 -> exact, order-independent) ----
    #pragma unroll
    for (int nt = 0; nt < 10; nt++) {
        const int row = mt * 16 + g;
        const int col = nt * 8 + 2 * t;
        atomicAdd(&g_cooc[(row)     * C + col],     d[nt][0]);
        atomicAdd(&g_cooc[(row)     * C + col + 1], d[nt][1]);
        atomicAdd(&g_cooc[(row + 8) * C + col],     d[nt][2]);
        atomicAdd(&g_cooc[(row + 8) * C + col + 1], d[nt][3]);
    }
}

__global__ void finalize_kernel(const float* __restrict__ pre_adj, float* __restrict__ out) {
    __shared__ float red[256];
    const int tid = threadIdx.x;
    float sum = 0.0f;
    for (int idx = tid; idx < C * C; idx += 256) {
        int i = idx / C, j = idx % C;
        float cooc = g_cooc[idx];
        float cnt  = g_cooc[i * C + i];          // diagonal = per-class count
        float adj  = (i == j) ? 1.0f : cooc / (cnt + 1e-7f);
        float r = fabsf(pre_adj[idx] - adj);
        sum += (r < 1.0f) ? (r * r) : (r - 0.5f);
    }
    red[tid] = sum;
    __syncthreads();                 // all g_cooc reads complete before re-zero
    // re-zero accumulator for the next (graph-replayed) launch
    for (int idx = tid; idx < C * C; idx += 256) g_cooc[idx] = 0.0f;
    for (int s = 128; s > 0; s >>= 1) {
        if (tid < s) red[tid] += red[tid + s];
        __syncthreads();
    }
    if (tid == 0) out[0] = red[0] / (float)(C * C);
}

extern "C" void kernel_launch(void* const* d_in, const int* in_sizes, int n_in,
                              void* d_out, int out_size) {
    const float* pre_adj = (const float*)d_in[0];
    const float* label   = (const float*)d_in[1];
    const int batch = in_sizes[1] / C;

    cooc_kernel<<<GRID, NTHREADS>>>(label, batch);
    finalize_kernel<<<1, 256>>>(pre_adj, (float*)d_out);
}

// round 3
// speedup vs baseline: 1.6857x; 1.1008x over previous
#include <cuda_runtime.h>
#include <cuda_bf16.h>
#include <cstdint>

#define C 80
#define KB 128                 // items per CTA tile
#define PITCH 88               // halves per item row (80 + 8 pad) -> 176 B, conflict-free ldmatrix
#define NWARPS 10              // 5 M-tiles x 2 K-groups (64 items each)
#define NTHREADS 320
#define GRID 304               // 2 CTAs per SM, grid-stride over tiles
#define LPT ((KB * C / 4) / NTHREADS)   // float4 loads per thread per tile = 8

__device__ float g_cooc[C * C];
__device__ unsigned int g_count;

__global__ __launch_bounds__(NTHREADS, 2)
void fused_kernel(const float* __restrict__ label,
                  const float* __restrict__ pre_adj,
                  float* __restrict__ out, int batch) {
    __shared__ __nv_bfloat16 sT[KB * PITCH];   // natural [item][class] bf16
    __shared__ float red[NWARPS];
    __shared__ int s_last;

    const int tid  = threadIdx.x;
    const int warp = tid >> 5;
    const int lane = tid & 31;
    const int mt   = warp % 5;   // M tile: classes mt*16 .. mt*16+15
    const int kg   = warp / 5;   // item group: kg*64 .. kg*64+63
    const int g    = lane >> 2;
    const int t    = lane & 3;
    const int gi   = lane >> 3;  // ldmatrix group 0..3
    const int li   = lane & 7;   // lane within group

    uint32_t smem_u32;
    { uint64_t tmp; asm("cvta.to.shared.u64 %0, %1;" : "=l"(tmp) : "l"((void*)sT));
      smem_u32 = (uint32_t)tmp; }

    const int a_cls   = mt * 16 + ((gi & 1) ? 8 : 0);
    const int a_kbase = ((gi & 2) ? 8 : 0) + li;
    const int b_clsadd = (gi & 2) ? 8 : 0;
    const int b_kbase  = ((gi & 1) ? 8 : 0) + li;

    float d[10][4];
    #pragma unroll
    for (int n = 0; n < 10; n++)
        #pragma unroll
        for (int q = 0; q < 4; q++) d[n][q] = 0.0f;

    const int numTiles = (batch + KB - 1) / KB;

    float4 st[LPT];                       // staged global loads for the CURRENT tile

    // ---- prologue: load first tile into registers ----
    int tile = blockIdx.x;
    if (tile < numTiles) {
        const long long base = (long long)tile * KB * C;
        #pragma unroll
        for (int p = 0; p < LPT; p++) {
            int idx  = tid + p * NTHREADS;
            int item = idx / (C / 4);
            int c4   = (idx % (C / 4)) * 4;
            st[p] = (tile * KB + item < batch)
                  ? *(const float4*)(label + base + (long long)item * C + c4)
                  : make_float4(0.f, 0.f, 0.f, 0.f);
        }
    }

    while (tile < numTiles) {
        // ---- convert staged regs -> bf16, store natural layout ----
        #pragma unroll
        for (int p = 0; p < LPT; p++) {
            int idx  = tid + p * NTHREADS;
            int item = idx / (C / 4);
            int c4   = (idx % (C / 4)) * 4;
            uint32_t lo, hi;
            asm("cvt.rn.bf16x2.f32 %0, %1, %2;" : "=r"(lo) : "f"(st[p].y), "f"(st[p].x));
            asm("cvt.rn.bf16x2.f32 %0, %1, %2;" : "=r"(hi) : "f"(st[p].w), "f"(st[p].z));
            *(uint2*)&sT[item * PITCH + c4] = make_uint2(lo, hi);
        }
        __syncthreads();

        // ---- issue NEXT tile's loads now; latency hidden under MMA phase ----
        const int nxt = tile + GRID;
        if (nxt < numTiles) {
            const long long base = (long long)nxt * KB * C;
            #pragma unroll
            for (int p = 0; p < LPT; p++) {
                int idx  = tid + p * NTHREADS;
                int item = idx / (C / 4);
                int c4   = (idx % (C / 4)) * 4;
                st[p] = (nxt * KB + item < batch)
                      ? *(const float4*)(label + base + (long long)item * C + c4)
                      : make_float4(0.f, 0.f, 0.f, 0.f);
            }
        }

        // ---- MMA phase on current smem tile ----
        #pragma unroll
        for (int ks = 0; ks < 4; ks++) {
            const int k0 = kg * 64 + ks * 16;

            uint32_t a0, a1, a2, a3;
            {
                uint32_t addr = smem_u32 + (uint32_t)(((k0 + a_kbase) * PITCH + a_cls) * 2);
                asm volatile("ldmatrix.sync.aligned.m8n8.x4.trans.shared.b16 "
                             "{%0,%1,%2,%3}, [%4];"
                             : "=r"(a0), "=r"(a1), "=r"(a2), "=r"(a3) : "r"(addr));
            }

            #pragma unroll
            for (int p = 0; p < 5; p++) {
                const int n0 = p * 16;
                uint32_t b0, b1, b2, b3;
                uint32_t addr = smem_u32 + (uint32_t)(((k0 + b_kbase) * PITCH + n0 + b_clsadd) * 2);
                asm volatile("ldmatrix.sync.aligned.m8n8.x4.trans.shared.b16 "
                             "{%0,%1,%2,%3}, [%4];"
                             : "=r"(b0), "=r"(b1), "=r"(b2), "=r"(b3) : "r"(addr));
                asm volatile(
                    "mma.sync.aligned.m16n8k16.row.col.f32.bf16.bf16.f32 "
                    "{%0,%1,%2,%3}, {%4,%5,%6,%7}, {%8,%9}, {%0,%1,%2,%3};\n"
                    : "+f"(d[2*p][0]), "+f"(d[2*p][1]), "+f"(d[2*p][2]), "+f"(d[2*p][3])
                    : "r"(a0), "r"(a1), "r"(a2), "r"(a3), "r"(b0), "r"(b1));
                asm volatile(
                    "mma.sync.aligned.m16n8k16.row.col.f32.bf16.bf16.f32 "
                    "{%0,%1,%2,%3}, {%4,%5,%6,%7}, {%8,%9}, {%0,%1,%2,%3};\n"
                    : "+f"(d[2*p+1][0]), "+f"(d[2*p+1][1]), "+f"(d[2*p+1][2]), "+f"(d[2*p+1][3])
                    : "r"(a0), "r"(a1), "r"(a2), "r"(a3), "r"(b2), "r"(b3));
            }
        }
        __syncthreads();
        tile = nxt;
    }

    // ---- flush partials (integer-valued f32 -> exact, order-independent) ----
    #pragma unroll
    for (int nt = 0; nt < 10; nt++) {
        const int row = mt * 16 + g;
        const int col = nt * 8 + 2 * t;
        atomicAdd(&g_cooc[(row)     * C + col],     d[nt][0]);
        atomicAdd(&g_cooc[(row)     * C + col + 1], d[nt][1]);
        atomicAdd(&g_cooc[(row + 8) * C + col],     d[nt][2]);
        atomicAdd(&g_cooc[(row + 8) * C + col + 1], d[nt][3]);
    }

    // ---- last-CTA finalize (fused; no second kernel) ----
    __threadfence();
    __syncthreads();
    if (tid == 0)
        s_last = (atomicAdd(&g_count, 1u) == (unsigned)gridDim.x - 1u) ? 1 : 0;
    __syncthreads();
    if (!s_last) return;

    float sum = 0.0f;
    for (int idx = tid; idx < C * C; idx += NTHREADS) {
        int i = idx / C, j = idx - i * C;
        float cooc = g_cooc[idx];
        float cnt  = g_cooc[i * C + i];
        float adj  = (i == j) ? 1.0f : __fdividef(cooc, cnt + 1e-7f);
        float r = fabsf(pre_adj[idx] - adj);
        sum += (r < 1.0f) ? (r * r) : (r - 0.5f);
    }
    #pragma unroll
    for (int o = 16; o > 0; o >>= 1) sum += __shfl_down_sync(0xffffffffu, sum, o);
    if (lane == 0) red[warp] = sum;
    __syncthreads();
    if (warp == 0) {
        float v = (lane < NWARPS) ? red[lane] : 0.0f;
        #pragma unroll
        for (int o = 16; o > 0; o >>= 1) v += __shfl_down_sync(0xffffffffu, v, o);
        if (lane == 0) out[0] = v / (float)(C * C);
    }
    __syncthreads();   // all g_cooc reads complete before re-zero
    for (int idx = tid; idx < C * C; idx += NTHREADS) g_cooc[idx] = 0.0f;
    if (tid == 0) g_count = 0u;
}

extern "C" void kernel_launch(void* const* d_in, const int* in_sizes, int n_in,
                              void* d_out, int out_size) {
    const float* pre_adj = (const float*)d_in[0];
    const float* label   = (const float*)d_in[1];
    const int batch = in_sizes[1] / C;

    fused_kernel<<<GRID, NTHREADS>>>(label, pre_adj, (float*)d_out, batch);
}

// round 4
// speedup vs baseline: 1.7584x; 1.0431x over previous
#include <cuda_runtime.h>
#include <cuda_bf16.h>
#include <cstdint>

#define C 80
#define KB 128                 // items per CTA tile
#define PITCH 88               // halves per item row (80 + 8 pad), conflict-free ldmatrix
#define NWARPS 10              // 5 M-tiles x 2 K-groups (64 items each)
#define NTHREADS 320
#define GRID 304               // 2 CTAs per SM, grid-stride over tiles
#define LPT ((KB * C / 4) / NTHREADS)   // float4 loads per thread per tile = 8

__device__ float g_cooc[C * C];
__device__ unsigned int g_count;

__global__ __launch_bounds__(NTHREADS, 2)
void fused_kernel(const float* __restrict__ label,
                  const float* __restrict__ pre_adj,
                  float* __restrict__ out, int batch) {
    __shared__ __nv_bfloat16 sT[2][KB * PITCH];   // double-buffered [item][class] bf16
    __shared__ float red[NWARPS];
    __shared__ int s_last;

    const int tid  = threadIdx.x;
    const int warp = tid >> 5;
    const int lane = tid & 31;
    const int mt   = warp % 5;   // M tile: classes mt*16 .. mt*16+15
    const int kg   = warp / 5;   // item group: kg*64 .. kg*64+63
    const int g    = lane >> 2;
    const int t    = lane & 3;
    const int gi   = lane >> 3;  // ldmatrix group 0..3
    const int li   = lane & 7;   // lane within group

    uint32_t smem_u32;
    { uint64_t tmp; asm("cvta.to.shared.u64 %0, %1;" : "=l"(tmp) : "l"((void*)&sT[0][0]));
      smem_u32 = (uint32_t)tmp; }

    const int a_cls    = mt * 16 + ((gi & 1) ? 8 : 0);
    const int a_kbase  = ((gi & 2) ? 8 : 0) + li;
    const int b_clsadd = (gi & 2) ? 8 : 0;
    const int b_kbase  = ((gi & 1) ? 8 : 0) + li;

    float d[10][4];
    #pragma unroll
    for (int n = 0; n < 10; n++)
        #pragma unroll
        for (int q = 0; q < 4; q++) d[n][q] = 0.0f;

    // per-thread staging-store coordinates
    const int st_item = tid / (C / 4);            // 0..15 (base item, +16 per p)
    const int st_c4   = (tid % (C / 4)) * 4;      // class offset

    const int numTiles = (batch + KB - 1) / KB;   // batch is an exact multiple of KB here

    float4 st[LPT];

    // ---- prologue: load first tile into registers ----
    int tile = blockIdx.x;
    if (tile < numTiles) {
        const float* p0 = label + (long long)tile * KB * C + (long long)st_item * C + st_c4;
        #pragma unroll
        for (int p = 0; p < LPT; p++)
            st[p] = *(const float4*)(p0 + (long long)p * 16 * C);
    }

    int pb = 0;                                   // smem buffer parity
    while (tile < numTiles) {
        // ---- store staged regs as bf16 (exact truncation for {0,1}) ----
        __nv_bfloat16* buf = &sT[pb][0];
        #pragma unroll
        for (int p = 0; p < LPT; p++) {
            uint32_t lo, hi;
            asm("prmt.b32 %0, %1, %2, 0x7632;" : "=r"(lo)
                : "r"(__float_as_uint(st[p].x)), "r"(__float_as_uint(st[p].y)));
            asm("prmt.b32 %0, %1, %2, 0x7632;" : "=r"(hi)
                : "r"(__float_as_uint(st[p].z)), "r"(__float_as_uint(st[p].w)));
            *(uint2*)&buf[(st_item + p * 16) * PITCH + st_c4] = make_uint2(lo, hi);
        }
        __syncthreads();   // ONLY sync: buf[pb] ready; also proves all warps done MMA(i-1)

        // ---- issue NEXT tile's loads; latency hidden under MMA phase ----
        const int nxt = tile + GRID;
        if (nxt < numTiles) {
            const float* p0 = label + (long long)nxt * KB * C + (long long)st_item * C + st_c4;
            #pragma unroll
            for (int p = 0; p < LPT; p++)
                st[p] = *(const float4*)(p0 + (long long)p * 16 * C);
        }

        // ---- MMA phase on current smem buffer ----
        const uint32_t sbase = smem_u32 + (uint32_t)(pb * KB * PITCH * 2);
        #pragma unroll
        for (int ks = 0; ks < 4; ks++) {
            const int k0 = kg * 64 + ks * 16;

            uint32_t a0, a1, a2, a3;
            {
                uint32_t addr = sbase + (uint32_t)(((k0 + a_kbase) * PITCH + a_cls) * 2);
                asm volatile("ldmatrix.sync.aligned.m8n8.x4.trans.shared.b16 "
                             "{%0,%1,%2,%3}, [%4];"
                             : "=r"(a0), "=r"(a1), "=r"(a2), "=r"(a3) : "r"(addr));
            }

            #pragma unroll
            for (int p = 0; p < 5; p++) {
                const int n0 = p * 16;
                uint32_t b0, b1, b2, b3;
                uint32_t addr = sbase + (uint32_t)(((k0 + b_kbase) * PITCH + n0 + b_clsadd) * 2);
                asm volatile("ldmatrix.sync.aligned.m8n8.x4.trans.shared.b16 "
                             "{%0,%1,%2,%3}, [%4];"
                             : "=r"(b0), "=r"(b1), "=r"(b2), "=r"(b3) : "r"(addr));
                asm volatile(
                    "mma.sync.aligned.m16n8k16.row.col.f32.bf16.bf16.f32 "
                    "{%0,%1,%2,%3}, {%4,%5,%6,%7}, {%8,%9}, {%0,%1,%2,%3};\n"
                    : "+f"(d[2*p][0]), "+f"(d[2*p][1]), "+f"(d[2*p][2]), "+f"(d[2*p][3])
                    : "r"(a0), "r"(a1), "r"(a2), "r"(a3), "r"(b0), "r"(b1));
                asm volatile(
                    "mma.sync.aligned.m16n8k16.row.col.f32.bf16.bf16.f32 "
                    "{%0,%1,%2,%3}, {%4,%5,%6,%7}, {%8,%9}, {%0,%1,%2,%3};\n"
                    : "+f"(d[2*p+1][0]), "+f"(d[2*p+1][1]), "+f"(d[2*p+1][2]), "+f"(d[2*p+1][3])
                    : "r"(a0), "r"(a1), "r"(a2), "r"(a3), "r"(b2), "r"(b3));
            }
        }
        tile = nxt;
        pb ^= 1;
    }

    // ---- flush partials (integer-valued f32 -> exact, order-independent) ----
    #pragma unroll
    for (int nt = 0; nt < 10; nt++) {
        const int row = mt * 16 + g;
        const int col = nt * 8 + 2 * t;
        atomicAdd(&g_cooc[(row)     * C + col],     d[nt][0]);
        atomicAdd(&g_cooc[(row)     * C + col + 1], d[nt][1]);
        atomicAdd(&g_cooc[(row + 8) * C + col],     d[nt][2]);
        atomicAdd(&g_cooc[(row + 8) * C + col + 1], d[nt][3]);
    }

    // ---- last-CTA finalize (fused; no second kernel) ----
    __threadfence();
    __syncthreads();
    if (tid == 0)
        s_last = (atomicAdd(&g_count, 1u) == (unsigned)gridDim.x - 1u) ? 1 : 0;
    __syncthreads();
    if (!s_last) return;

    float sum = 0.0f;
    for (int idx = tid; idx < C * C; idx += NTHREADS) {
        int i = idx / C, j = idx - i * C;
        float cooc = g_cooc[idx];
        float cnt  = g_cooc[i * C + i];
        float adj  = (i == j) ? 1.0f : __fdividef(cooc, cnt + 1e-7f);
        float r = fabsf(pre_adj[idx] - adj);
        sum += (r < 1.0f) ? (r * r) : (r - 0.5f);
    }
    #pragma unroll
    for (int o = 16; o > 0; o >>= 1) sum += __shfl_down_sync(0xffffffffu, sum, o);
    if (lane == 0) red[warp] = sum;
    __syncthreads();
    if (warp == 0) {
        float v = (lane < NWARPS) ? red[lane] : 0.0f;
        #pragma unroll
        for (int o = 16; o > 0; o >>= 1) v += __shfl_down_sync(0xffffffffu, v, o);
        if (lane == 0) out[0] = v / (float)(C * C);
    }
    __syncthreads();   // all g_cooc reads complete before re-zero
    for (int idx = tid; idx < C * C; idx += NTHREADS) g_cooc[idx] = 0.0f;
    if (tid == 0) g_count = 0u;
}

extern "C" void kernel_launch(void* const* d_in, const int* in_sizes, int n_in,
                              void* d_out, int out_size) {
    const float* pre_adj = (const float*)d_in[0];
    const float* label   = (const float*)d_in[1];
    const int batch = in_sizes[1] / C;

    fused_kernel<<<GRID, NTHREADS>>>(label, pre_adj, (float*)d_out, batch);
}

// round 6
// speedup vs baseline: 1.9943x; 1.1341x over previous
#include <cuda_runtime.h>
#include <cuda_bf16.h>
#include <cstdint>

#define C 80
#define KB 64                  // items per CTA tile
#define PITCH 88               // halves per item row (80 + 8 pad), conflict-free ldmatrix
#define NWARPS 5
#define NTHREADS 160
#define GRID 592               // 4 CTAs per SM x 148
#define LPT ((KB * C / 4) / NTHREADS)   // float4 loads per thread per tile = 8

__device__ float g_cooc[C * C];
__device__ unsigned int g_count;

__global__ __launch_bounds__(NTHREADS, 4)
void fused_kernel(const float* __restrict__ label,
                  const float* __restrict__ pre_adj,
                  float* __restrict__ out, int batch) {
    __shared__ __nv_bfloat16 sT[2][KB * PITCH];   // double-buffered [item][class] bf16
    __shared__ float red[NWARPS];
    __shared__ int s_last;

    const int tid  = threadIdx.x;
    const int warp = tid >> 5;     // 0..4 : row-block w
    const int lane = tid & 31;
    const int g    = lane >> 2;
    const int t    = lane & 3;
    const int gi   = lane >> 3;    // ldmatrix group 0..3
    const int li   = lane & 7;

    uint32_t smem_u32;
    { uint64_t tmp; asm("cvta.to.shared.u64 %0, %1;" : "=l"(tmp) : "l"((void*)&sT[0][0]));
      smem_u32 = (uint32_t)tmp; }

    // trans-ldmatrix geometry (proven in R2-R4):
    // A: class col = w*16 + ((gi&1)?8:0), item row = ((gi&2)?8:0)+li
    const int a_cls    = warp * 16 + ((gi & 1) ? 8 : 0);
    const int a_kbase  = ((gi & 2) ? 8 : 0) + li;
    // B: class col = bj*16 + ((gi&2)?8:0), item row = ((gi&1)?8:0)+li
    const int b_clsadd = (gi & 2) ? 8 : 0;
    const int b_kbase  = ((gi & 1) ? 8 : 0) + li;

    // this warp's three col-blocks (unordered block pairs covered exactly once)
    const int bj0 = warp;
    const int bj1 = (warp + 1) % 5;
    const int bj2 = (warp + 2) % 5;

    float d[3][2][4];
    #pragma unroll
    for (int b = 0; b < 3; b++)
        #pragma unroll
        for (int n = 0; n < 2; n++)
            #pragma unroll
            for (int q = 0; q < 4; q++) d[b][n][q] = 0.0f;

    // fill coordinates: 1280 float4 over 160 threads -> 8 each
    const int st_item = tid / (C / 4);            // 0..7 (base item; +8 per p)
    const int st_c4   = (tid % (C / 4)) * 4;

    const int numTiles = (batch + KB - 1) / KB;

    float4 st[LPT];
    int tile = blockIdx.x;
    if (tile < numTiles) {
        const float* p0 = label + (long long)tile * KB * C + (long long)st_item * C + st_c4;
        #pragma unroll
        for (int p = 0; p < LPT; p++)
            st[p] = *(const float4*)(p0 + (long long)p * 8 * C);
    }

    int pb = 0;
    while (tile < numTiles) {
        // ---- store staged regs as bf16 (exact truncation for {0,1}) ----
        __nv_bfloat16* buf = &sT[pb][0];
        #pragma unroll
        for (int p = 0; p < LPT; p++) {
            uint32_t lo, hi;
            asm("prmt.b32 %0, %1, %2, 0x7632;" : "=r"(lo)
                : "r"(__float_as_uint(st[p].x)), "r"(__float_as_uint(st[p].y)));
            asm("prmt.b32 %0, %1, %2, 0x7632;" : "=r"(hi)
                : "r"(__float_as_uint(st[p].z)), "r"(__float_as_uint(st[p].w)));
            *(uint2*)&buf[(st_item + p * 8) * PITCH + st_c4] = make_uint2(lo, hi);
        }
        __syncthreads();   // buf[pb] ready; also proves all warps done MMA(i-1)

        // ---- prefetch next tile; latency hidden under MMA phase ----
        const int nxt = tile + GRID;
        if (nxt < numTiles) {
            const float* p0 = label + (long long)nxt * KB * C + (long long)st_item * C + st_c4;
            #pragma unroll
            for (int p = 0; p < LPT; p++)
                st[p] = *(const float4*)(p0 + (long long)p * 8 * C);
        }

        // ---- MMA phase: row-block w vs col-blocks {bj0,bj1,bj2}, K=64 ----
        const uint32_t sbase = smem_u32 + (uint32_t)(pb * KB * PITCH * 2);
        #pragma unroll
        for (int ks = 0; ks < 4; ks++) {
            const int k0 = ks * 16;

            uint32_t a0, a1, a2, a3;
            {
                uint32_t addr = sbase + (uint32_t)(((k0 + a_kbase) * PITCH + a_cls) * 2);
                asm volatile("ldmatrix.sync.aligned.m8n8.x4.trans.shared.b16 "
                             "{%0,%1,%2,%3}, [%4];"
                             : "=r"(a0), "=r"(a1), "=r"(a2), "=r"(a3) : "r"(addr));
            }

            const int bjs[3] = {bj0, bj1, bj2};
            #pragma unroll
            for (int b = 0; b < 3; b++) {
                const int n0 = bjs[b] * 16;
                uint32_t b0, b1, b2, b3;
                uint32_t addr = sbase + (uint32_t)(((k0 + b_kbase) * PITCH + n0 + b_clsadd) * 2);
                asm volatile("ldmatrix.sync.aligned.m8n8.x4.trans.shared.b16 "
                             "{%0,%1,%2,%3}, [%4];"
                             : "=r"(b0), "=r"(b1), "=r"(b2), "=r"(b3) : "r"(addr));
                asm volatile(
                    "mma.sync.aligned.m16n8k16.row.col.f32.bf16.bf16.f32 "
                    "{%0,%1,%2,%3}, {%4,%5,%6,%7}, {%8,%9}, {%0,%1,%2,%3};\n"
                    : "+f"(d[b][0][0]), "+f"(d[b][0][1]), "+f"(d[b][0][2]), "+f"(d[b][0][3])
                    : "r"(a0), "r"(a1), "r"(a2), "r"(a3), "r"(b0), "r"(b1));
                asm volatile(
                    "mma.sync.aligned.m16n8k16.row.col.f32.bf16.bf16.f32 "
                    "{%0,%1,%2,%3}, {%4,%5,%6,%7}, {%8,%9}, {%0,%1,%2,%3};\n"
                    : "+f"(d[b][1][0]), "+f"(d[b][1][1]), "+f"(d[b][1][2]), "+f"(d[b][1][3])
                    : "r"(a0), "r"(a1), "r"(a2), "r"(a3), "r"(b2), "r"(b3));
            }
        }
        tile = nxt;
        pb ^= 1;
    }

    // ---- flush partials (integer-valued f32 -> exact, order-independent) ----
    {
        const int bjs[3] = {bj0, bj1, bj2};
        #pragma unroll
        for (int b = 0; b < 3; b++) {
            const int row = warp * 16 + g;
            #pragma unroll
            for (int n = 0; n < 2; n++) {
                const int col = bjs[b] * 16 + n * 8 + 2 * t;
                atomicAdd(&g_cooc[(row)     * C + col],     d[b][n][0]);
                atomicAdd(&g_cooc[(row)     * C + col + 1], d[b][n][1]);
                atomicAdd(&g_cooc[(row + 8) * C + col],     d[b][n][2]);
                atomicAdd(&g_cooc[(row + 8) * C + col + 1], d[b][n][3]);
            }
        }
    }

    // ---- last-CTA finalize ----
    __threadfence();
    __syncthreads();
    if (tid == 0)
        s_last = (atomicAdd(&g_count, 1u) == (unsigned)gridDim.x - 1u) ? 1 : 0;
    __syncthreads();
    if (!s_last) return;

    float sum = 0.0f;
    for (int idx = tid; idx < C * C; idx += NTHREADS) {
        int i = idx / C, j = idx - i * C;
        int bi = i >> 4, bj = j >> 4;
        int dd = bj - bi; if (dd < 0) dd += 5;
        float cooc = (dd <= 2) ? g_cooc[i * C + j] : g_cooc[j * C + i];  // symmetry mirror
        float cnt  = g_cooc[i * C + i];
        float adj  = (i == j) ? 1.0f : __fdividef(cooc, cnt + 1e-7f);
        float r = fabsf(pre_adj[idx] - adj);
        sum += (r < 1.0f) ? (r * r) : (r - 0.5f);
    }
    #pragma unroll
    for (int o = 16; o > 0; o >>= 1) sum += __shfl_down_sync(0xffffffffu, sum, o);
    if (lane == 0) red[warp] = sum;
    __syncthreads();
    if (warp == 0) {
        float v = (lane < NWARPS) ? red[lane] : 0.0f;
        #pragma unroll
        for (int o = 16; o > 0; o >>= 1) v += __shfl_down_sync(0xffffffffu, v, o);
        if (lane == 0) out[0] = v / (float)(C * C);
    }
    __syncthreads();   // all g_cooc reads complete before re-zero
    for (int idx = tid; idx < C * C; idx += NTHREADS) g_cooc[idx] = 0.0f;
    if (tid == 0) g_count = 0u;
}

extern "C" void kernel_launch(void* const* d_in, const int* in_sizes, int n_in,
                              void* d_out, int out_size) {
    const float* pre_adj = (const float*)d_in[0];
    const float* label   = (const float*)d_in[1];
    const int batch = in_sizes[1] / C;

    fused_kernel<<<GRID, NTHREADS>>>(label, pre_adj, (float*)d_out, batch);
}